// round 13
// baseline (speedup 1.0000x reference)
#include <cuda_runtime.h>
#include <cuda_bf16.h>
#include <math.h>
#include <stdint.h>

#define Bz 32
#define Lz 768
#define Dz 256
#define Fz 256
#define Tz 3072

#define NCONV 384                       // conv tile CTAs per layer (M=64)
// fused grid block ranges
#define BLK_CS   NCONV                  // 32 cumsum
#define BLK_C2   (BLK_CS + Bz)          // 384 conv2 tiles
#define BLK_GA   (BLK_C2 + NCONV)       // 1536 gather
#define BLK_TOTAL (BLK_GA + 48 * Bz)    // 2336

// prep_all dispatch ranges
#define PREP_X_BLOCKS 3072              // 6,291,456 / 2048
#define PREP_W_BLOCKS 1536              // 2 tensors x 196,608 / 256  (FIXED: was 768)
#define PREP_TOTAL (PREP_X_BLOCKS + PREP_W_BLOCKS + 1)

#define NFLAGS (NCONV + Bz)

// ---------------------------------------------------------------------------
// Scratch (allocation-free: __device__ globals)
// ---------------------------------------------------------------------------
__device__ int8_t g_xa0[Bz * Lz * Dz];      // x hi slice (s8): a16 = x*2^12 = 256*a0+a1
__device__ int8_t g_xa1[Bz * Lz * Dz];      // x lo slice
__device__ int8_t g_h1a0[Bz * Lz * Fz];
__device__ int8_t g_h1a1[Bz * Lz * Fz];
// weights: [tap][cout][cin] s8 slices, b16 = w*2^17 = 256*b0+b1
__device__ int8_t g_w1b0[3 * 256 * 256];
__device__ int8_t g_w1b1[3 * 256 * 256];
__device__ int8_t g_w2b0[3 * 256 * 256];
__device__ int8_t g_w2b1[3 * 256 * 256];
__device__ float  g_glw[256];
__device__ float  g_scal[2];
__device__ int    g_cum[Bz * Lz];
__device__ int    g_flag[NFLAGS];

// ---------------------------------------------------------------------------
// helpers
// ---------------------------------------------------------------------------
__device__ __forceinline__ uint32_t smem_u32(const void* p) {
    uint32_t a;
    asm("{ .reg .u64 t; cvta.to.shared.u64 t, %1; cvt.u32.u64 %0, t; }"
        : "=r"(a) : "l"(p));
    return a;
}

__device__ __forceinline__ void cp16(uint32_t dst, const void* src, int src_bytes) {
    asm volatile("cp.async.cg.shared.global [%0], [%1], 16, %2;"
                 :: "r"(dst), "l"(src), "r"(src_bytes) : "memory");
}
#define CP_COMMIT() asm volatile("cp.async.commit_group;" ::: "memory")
#define CP_WAIT(n)  asm volatile("cp.async.wait_group %0;" :: "n"(n) : "memory")

#define LDSM_X4(r, addr) \
    asm volatile("ldmatrix.sync.aligned.m8n8.x4.shared.b16 {%0,%1,%2,%3}, [%4];" \
        : "=r"((r)[0]), "=r"((r)[1]), "=r"((r)[2]), "=r"((r)[3]) : "r"(addr))

// s8 MMA m16n8k32 with s32 accumulate (non-volatile: let ptxas schedule)
__device__ __forceinline__ void mma_s8(int* c, const uint32_t* a,
                                       uint32_t b0, uint32_t b1)
{
    asm("mma.sync.aligned.m16n8k32.row.col.s32.s8.s8.s32 "
        "{%0,%1,%2,%3}, {%4,%5,%6,%7}, {%8,%9}, {%0,%1,%2,%3};\n"
        : "+r"(c[0]), "+r"(c[1]), "+r"(c[2]), "+r"(c[3])
        : "r"(a[0]), "r"(a[1]), "r"(a[2]), "r"(a[3]), "r"(b0), "r"(b1));
}

// fixed-point 16-bit quantize + split into two s8 slices (a16 = 256*q0 + q1)
__device__ __forceinline__ void q16(float v, float scale, int& q0, int& q1)
{
    int a16 = __float2int_rn(v * scale);
    a16 = max(-32640, min(32639, a16));
    q0 = (a16 + 128) >> 8;
    q1 = a16 - (q0 << 8);
}

__device__ __forceinline__ void flag_publish(int idx) {
    __threadfence();
    if (threadIdx.x == 0) atomicExch(&g_flag[idx], 1);
}
__device__ __forceinline__ void flag_spin(int idx) {
    if (threadIdx.x == 0) {
        while (atomicAdd(&g_flag[idx], 0) == 0) __nanosleep(64);
    }
}

// ---------------------------------------------------------------------------
// Unified prep kernel (256 threads/block)
// ---------------------------------------------------------------------------
__global__ __launch_bounds__(256)
void prep_all(const float* __restrict__ x,
              int8_t* __restrict__ xa0, int8_t* __restrict__ xa1,
              const float* __restrict__ w1, const float* __restrict__ w2,
              int8_t* __restrict__ w1b0, int8_t* __restrict__ w1b1,
              int8_t* __restrict__ w2b0, int8_t* __restrict__ w2b1,
              const float* __restrict__ g, const float* __restrict__ bb,
              const float* __restrict__ lw, const float* __restrict__ lb,
              float* __restrict__ glw, float* __restrict__ scal)
{
    const int blk = blockIdx.x;
    const int t = threadIdx.x;

    if (blk < PREP_X_BLOCKS) {
        size_t i = ((size_t)blk * 256 + t) * 8;
        float4 f0 = *(const float4*)(x + i);
        float4 f1 = *(const float4*)(x + i + 4);
        float vs[8] = {f0.x, f0.y, f0.z, f0.w, f1.x, f1.y, f1.z, f1.w};
        uint32_t p0[2] = {0, 0}, p1[2] = {0, 0};
#pragma unroll
        for (int j = 0; j < 8; ++j) {
            int q0, q1;
            q16(vs[j], 4096.f, q0, q1);
            p0[j >> 2] |= ((uint32_t)(uint8_t)q0) << ((j & 3) * 8);
            p1[j >> 2] |= ((uint32_t)(uint8_t)q1) << ((j & 3) * 8);
        }
        *(uint2*)(xa0 + i) = make_uint2(p0[0], p0[1]);
        *(uint2*)(xa1 + i) = make_uint2(p1[0], p1[1]);
        return;
    }
    if (blk < PREP_X_BLOCKS + PREP_W_BLOCKS) {
        int e = blk - PREP_X_BLOCKS;                   // 0..1535
        int sel = e >= 768;
        int idx = (e - sel * 768) * 256 + t;           // 0 .. 196607
        const float* w = sel ? w2 : w1;
        int8_t* b0p = sel ? w2b0 : w1b0;
        int8_t* b1p = sel ? w2b1 : w1b1;
        int cin  = idx & 255;
        int cout = (idx >> 8) & 255;
        int tap  = idx >> 16;                          // 0..2
        float v = w[((size_t)(tap * 256 + cin)) * 256 + cout];
        int q0, q1;
        q16(v, 131072.f, q0, q1);
        b0p[idx] = (int8_t)q0;
        b1p[idx] = (int8_t)q1;
        return;
    }
    // scalars + flag reset
    {
        for (int i = t; i < NFLAGS; i += 256) g_flag[i] = 0;
        __shared__ float sg[8], sb[8];
        float lwv = lw[t];
        float gv = g[t] * lwv;
        float bv = bb[t] * lwv;
        glw[t] = gv;
#pragma unroll
        for (int o = 16; o; o >>= 1) {
            gv += __shfl_xor_sync(0xffffffffu, gv, o);
            bv += __shfl_xor_sync(0xffffffffu, bv, o);
        }
        if ((t & 31) == 0) { sg[t >> 5] = gv; sb[t >> 5] = bv; }
        __syncthreads();
        if (t == 0) {
            float G = 0.f, Bv = 0.f;
            for (int i = 0; i < 8; i++) { G += sg[i]; Bv += sb[i]; }
            scal[0] = G;
            scal[1] = Bv + lb[0];
        }
    }
}

// ---------------------------------------------------------------------------
// cumsum for one batch (512-thread block; threads 0..255 active)
// ---------------------------------------------------------------------------
__device__ void cumsum_block(int b, const int* __restrict__ target,
                             float* __restrict__ dpo_out, char* smem)
{
    int* ps = (int*)smem;
    const int t = threadIdx.x;
    int v0 = 0, v1 = 0, v2 = 0, s1 = 0, s2 = 0;
    const size_t base = (size_t)b * Lz + 3 * t;
    if (t < 256) {
        v0 = target[base]; v1 = target[base + 1]; v2 = target[base + 2];
        s1 = v0 + v1; s2 = s1 + v2;
        ps[t] = s2;
    }
    __syncthreads();
#pragma unroll
    for (int off = 1; off < 256; off <<= 1) {
        int u = (t >= off && t < 256) ? ps[t - off] : 0;
        __syncthreads();
        if (t < 256) ps[t] += u;
        __syncthreads();
    }
    if (t < 256) {
        int pre = (t > 0) ? ps[t - 1] : 0;
        g_cum[base]     = pre + v0;
        g_cum[base + 1] = pre + s1;
        g_cum[base + 2] = pre + s2;
        dpo_out[base]     = (float)v0;
        dpo_out[base + 1] = (float)v1;
        dpo_out[base + 2] = (float)v2;
    }
    __syncthreads();
    flag_publish(NCONV + b);
}

// ---------------------------------------------------------------------------
// gather for one (batch, 64-t block), 512 threads
// ---------------------------------------------------------------------------
__device__ void gather_block(int e, const float* __restrict__ x,
                             float* __restrict__ dout, char* smem)
{
    int* cum = (int*)smem;
    const int b = e / 48;
    const int tpart = e % 48;
    const int tid = threadIdx.x;

    flag_spin(NCONV + b);
    __syncthreads();

    for (int i = tid; i < Lz; i += 512)
        cum[i] = g_cum[(size_t)b * Lz + i];
    __syncthreads();

    const int total = cum[Lz - 1];
    const int t0 = tpart * 64;
    const int sub  = tid & 63;
    const int tloc = tid >> 6;

    const float4* xrow = (const float4*)(x + (size_t)b * Lz * Dz);
    float4* orow = (float4*)(dout + (size_t)b * Tz * Dz);

#pragma unroll
    for (int it = 0; it < 8; ++it) {
        int t = t0 + it * 8 + tloc;
        int lo = 0, hi = Lz;
        while (lo < hi) {
            int mid = (lo + hi) >> 1;
            if (cum[mid] <= t) lo = mid + 1; else hi = mid;
        }
        float4 v;
        if (t < total) {
            int idx = min(lo, Lz - 1);
            v = xrow[(size_t)idx * 64 + sub];
        } else {
            v = make_float4(0.0f, 0.0f, 0.0f, 0.0f);
        }
        orow[(size_t)t * 64 + sub] = v;
    }
}

// ---------------------------------------------------------------------------
// conv tile: M=64 x N=256, 512 threads (16 warps 4M x 4N, warp tile 16x64),
// int8 m16n8k32 MMA, two s32 accumulator sets (P00, Pm=P01+P10),
// 3-stage cp.async pipeline, 12 chunks of K=64 (3 taps x 4 cin-blocks).
// ---------------------------------------------------------------------------
#define SA0 0
#define SA1 5120
#define SB0 10240
#define SB1 30720
#define STAGE 51200
#define STAGE0_OFF 4096
#define CONV_SMEM (STAGE0_OFF + 3 * STAGE)   // 157696

__device__ __forceinline__ void load_chunk(
    uint32_t stg, int c, int tid, int l0, size_t rowbase,
    const int8_t* __restrict__ Aa0, const int8_t* __restrict__ Aa1,
    const int8_t* __restrict__ Wb0, const int8_t* __restrict__ Wb1)
{
    const int tap  = c >> 2;
    const int cin0 = (c & 3) << 6;
    // A: 64 rows x 64B x 2 planes; one (plane,row,seg) per thread (512 jobs)
    {
        int plane = tid >> 8;
        int rr = tid & 255;
        int row = rr >> 2, seg = rr & 3;
        int gl = l0 + row + tap - 1;
        int ok = (gl >= 0 && gl < Lz) ? 16 : 0;
        int glc = gl < 0 ? 0 : (gl >= Lz ? Lz - 1 : gl);
        const int8_t* src = (plane ? Aa1 : Aa0) + ((rowbase + glc) << 8) + cin0 + (seg << 4);
        cp16(stg + (plane ? SA1 : SA0) + row * 80 + seg * 16, src, ok);
    }
    // B: 256 n x 64B x 2 planes = 2048 jobs, 4 per thread
#pragma unroll
    for (int i = 0; i < 4; ++i) {
        int idx = tid + (i << 9);
        int plane = idx >> 10;
        int rr = idx & 1023;
        int n = rr >> 2, seg = rr & 3;
        const int8_t* src = (plane ? Wb1 : Wb0) + ((size_t)tap << 16) + (n << 8) + cin0 + (seg << 4);
        cp16(stg + (plane ? SB1 : SB0) + n * 80 + seg * 16, src, 16);
    }
}

__device__ void conv_tile(
    int tile, bool fin, char* smem,
    const int8_t* __restrict__ Aa0, const int8_t* __restrict__ Aa1,
    const int8_t* __restrict__ Wb0, const int8_t* __restrict__ Wb1,
    const float* __restrict__ bias, const float* __restrict__ gamma,
    const float* __restrict__ beta, const float* __restrict__ glw,
    const float* __restrict__ scal,
    int8_t* __restrict__ out0, int8_t* __restrict__ out1,
    float* __restrict__ dur)
{
    const uint32_t sb = smem_u32(smem);
    float* svec = (float*)smem;                       // [4][256]
    const uint32_t stage0 = sb + STAGE0_OFF;

    const int tid = threadIdx.x;
    const int wid = tid >> 5, lane = tid & 31;
    const int wm = wid >> 2, wn = wid & 3;            // 4M x 4N warps
    const int grp = lane >> 2, tig = lane & 3;

    const int batch = tile / 12;
    const int part  = tile % 12;
    const int l0 = part * 64;
    const size_t rowbase = (size_t)batch * Lz;

    if (fin) {
        flag_spin(tile);
        if (part > 0)  flag_spin(tile - 1);
        if (part < 11) flag_spin(tile + 1);
        __threadfence();
    }
    __syncthreads();

    if (tid < 256) {
        svec[tid]       = bias[tid];
        svec[256 + tid] = gamma[tid];
        svec[512 + tid] = beta[tid];
        svec[768 + tid] = fin ? glw[tid] : 0.f;
    }

    // ldmatrix per-lane byte offsets (within a stage)
    const uint32_t a_off = (uint32_t)((wm * 16 + (lane & 15)) * 80 + (lane >> 4) * 16);
    const uint32_t b_row = (uint32_t)(wn * 64 + (lane & 7) + ((lane >> 4) << 3));
    const uint32_t b_off = b_row * 80 + (((lane >> 3) & 1) << 4);

    int acc00[8][4], accm[8][4];
#pragma unroll
    for (int nt = 0; nt < 8; nt++)
#pragma unroll
        for (int i = 0; i < 4; i++) { acc00[nt][i] = 0; accm[nt][i] = 0; }

    load_chunk(stage0,             0, tid, l0, rowbase, Aa0, Aa1, Wb0, Wb1);
    CP_COMMIT();
    load_chunk(stage0 + STAGE,     1, tid, l0, rowbase, Aa0, Aa1, Wb0, Wb1);
    CP_COMMIT();

    int stg_idx = 0;
    for (int c = 0; c < 12; ++c) {
        const uint32_t stg = stage0 + stg_idx * STAGE;
        if (c < 11) CP_WAIT(1); else CP_WAIT(0);
        __syncthreads();

        if (c + 2 < 12) {
            int nidx = stg_idx + 2; if (nidx >= 3) nidx -= 3;
            load_chunk(stage0 + nidx * STAGE, c + 2, tid, l0, rowbase, Aa0, Aa1, Wb0, Wb1);
            CP_COMMIT();
        }

#pragma unroll
        for (int ks = 0; ks < 2; ++ks) {
            uint32_t af0[4], af1[4];
            LDSM_X4(af0, stg + SA0 + a_off + ks * 32);
            LDSM_X4(af1, stg + SA1 + a_off + ks * 32);
#pragma unroll
            for (int j = 0; j < 4; ++j) {
                uint32_t bf0[4], bf1[4];
                LDSM_X4(bf0, stg + SB0 + b_off + j * (16 * 80) + ks * 32);
                LDSM_X4(bf1, stg + SB1 + b_off + j * (16 * 80) + ks * 32);
                // P00 += a0*b0 ; Pm += a0*b1 + a1*b0
                mma_s8(acc00[2 * j],     af0, bf0[0], bf0[1]);
                mma_s8(acc00[2 * j + 1], af0, bf0[2], bf0[3]);
                mma_s8(accm[2 * j],      af0, bf1[0], bf1[1]);
                mma_s8(accm[2 * j + 1],  af0, bf1[2], bf1[3]);
                mma_s8(accm[2 * j],      af1, bf0[0], bf0[1]);
                mma_s8(accm[2 * j + 1],  af1, bf0[2], bf0[3]);
            }
        }
        if (++stg_idx == 3) stg_idx = 0;
    }
    __syncthreads();   // stage region free -> epilogue overlay

    // ----- epilogue: v = P00*2^-13 + Pm*2^-21 ; +bias, relu, LN [,lin+exp] --
    float* pa  = (float*)(smem + STAGE0_OFF);     // [3][64][4]
    float* smu = pa + 3 * 64 * 4;
    float* srs = smu + 64;

    float vals[2][8][2];   // [hf][nt][k]
#pragma unroll
    for (int hf = 0; hf < 2; ++hf) {
        float s = 0.f, sq = 0.f, sd = 0.f;
#pragma unroll
        for (int nt = 0; nt < 8; ++nt) {
            int col = wn * 64 + nt * 8 + 2 * tig;
#pragma unroll
            for (int k = 0; k < 2; ++k) {
                float v = (float)acc00[nt][hf * 2 + k] * 1.220703125e-4f
                        + (float)accm[nt][hf * 2 + k] * 4.76837158203125e-7f;
                v = fmaxf(v + svec[col + k], 0.f);
                vals[hf][nt][k] = v;
                s += v;
                sq += v * v;
                if (fin) sd += v * svec[768 + col + k];
            }
        }
        s  += __shfl_xor_sync(0xffffffffu, s, 1);
        s  += __shfl_xor_sync(0xffffffffu, s, 2);
        sq += __shfl_xor_sync(0xffffffffu, sq, 1);
        sq += __shfl_xor_sync(0xffffffffu, sq, 2);
        if (fin) {
            sd += __shfl_xor_sync(0xffffffffu, sd, 1);
            sd += __shfl_xor_sync(0xffffffffu, sd, 2);
        }
        if (tig == 0) {
            int row = wm * 16 + hf * 8 + grp;
            pa[0 * 256 + row * 4 + wn] = s;
            pa[1 * 256 + row * 4 + wn] = sq;
            if (fin) pa[2 * 256 + row * 4 + wn] = sd;
        }
    }
    __syncthreads();

    if (tid < 64) {
        int row = tid;
        float s  = pa[row * 4] + pa[row * 4 + 1] + pa[row * 4 + 2] + pa[row * 4 + 3];
        float sq = pa[256 + row * 4] + pa[256 + row * 4 + 1] +
                   pa[256 + row * 4 + 2] + pa[256 + row * 4 + 3];
        float mu  = s * (1.f / 256.f);
        float var = sq * (1.f / 256.f) - mu * mu;
        float rs  = rsqrtf(var + 1e-5f);
        if (fin) {
            float s3 = pa[512 + row * 4] + pa[512 + row * 4 + 1] +
                       pa[512 + row * 4 + 2] + pa[512 + row * 4 + 3];
            dur[(size_t)tile * 64 + row] = expf(rs * (s3 - mu * scal[0]) + scal[1]);
        } else {
            smu[row] = mu;
            srs[row] = rs;
        }
    }

    if (!fin) {
        __syncthreads();
#pragma unroll
        for (int hf = 0; hf < 2; ++hf) {
            int row = wm * 16 + hf * 8 + grp;
            float mu = smu[row], rs = srs[row];
#pragma unroll
            for (int nt = 0; nt < 8; ++nt) {
                int col = wn * 64 + nt * 8 + 2 * tig;
                float v0 = (vals[hf][nt][0] - mu) * rs * svec[256 + col]     + svec[512 + col];
                float v1 = (vals[hf][nt][1] - mu) * rs * svec[256 + col + 1] + svec[512 + col + 1];
                int q00, q01, q10, q11;
                q16(v0, 4096.f, q00, q01);
                q16(v1, 4096.f, q10, q11);
                size_t off = ((size_t)tile * 64 + row) * 256 + col;
                *(uint16_t*)(out0 + off) = (uint16_t)((uint8_t)q00 | ((uint16_t)(uint8_t)q10 << 8));
                *(uint16_t*)(out1 + off) = (uint16_t)((uint8_t)q01 | ((uint16_t)(uint8_t)q11 << 8));
            }
        }
        __syncthreads();   // ALL threads' h1 writes done before publish
        flag_publish(tile);
    }
}

// ---------------------------------------------------------------------------
// Fused pipeline kernel: conv1 | cumsum | conv2(+lin+exp) | gather
// ---------------------------------------------------------------------------
__global__ void __launch_bounds__(512, 1)
fused_all(const int8_t* __restrict__ xa0, const int8_t* __restrict__ xa1,
          int8_t* __restrict__ h1a0, int8_t* __restrict__ h1a1,
          const int8_t* __restrict__ w1b0, const int8_t* __restrict__ w1b1,
          const int8_t* __restrict__ w2b0, const int8_t* __restrict__ w2b1,
          const float* __restrict__ conv1_b, const float* __restrict__ ln1_g,
          const float* __restrict__ ln1_b,
          const float* __restrict__ conv2_b, const float* __restrict__ ln2_g,
          const float* __restrict__ ln2_b,
          const float* __restrict__ glw, const float* __restrict__ scal,
          const int* __restrict__ target, const float* __restrict__ x,
          float* __restrict__ out_gather, float* __restrict__ out_dpo,
          float* __restrict__ out_dur)
{
    extern __shared__ char smem[];
    const int blk = blockIdx.x;

    if (blk < BLK_CS) {
        conv_tile(blk, false, smem, xa0, xa1, w1b0, w1b1,
                  conv1_b, ln1_g, ln1_b, glw, scal, h1a0, h1a1, nullptr);
    } else if (blk < BLK_C2) {
        cumsum_block(blk - BLK_CS, target, out_dpo, smem);
    } else if (blk < BLK_GA) {
        conv_tile(blk - BLK_C2, true, smem, h1a0, h1a1, w2b0, w2b1,
                  conv2_b, ln2_g, ln2_b, glw, scal, nullptr, nullptr, out_dur);
    } else {
        gather_block(blk - BLK_GA, x, out_gather, smem);
    }
}

// ---------------------------------------------------------------------------
// Launch
// ---------------------------------------------------------------------------
extern "C" void kernel_launch(void* const* d_in, const int* in_sizes, int n_in,
                              void* d_out, int out_size)
{
    const float* x       = (const float*)d_in[0];
    const int*   target  = (const int*)  d_in[1];
    const float* conv1_w = (const float*)d_in[3];
    const float* conv1_b = (const float*)d_in[4];
    const float* ln1_g   = (const float*)d_in[5];
    const float* ln1_b   = (const float*)d_in[6];
    const float* conv2_w = (const float*)d_in[7];
    const float* conv2_b = (const float*)d_in[8];
    const float* ln2_g   = (const float*)d_in[9];
    const float* ln2_b   = (const float*)d_in[10];
    const float* lin_w   = (const float*)d_in[11];
    const float* lin_b   = (const float*)d_in[12];

    float* out_gather = (float*)d_out;                        // [B, T, D]
    float* out_dpo    = out_gather + (size_t)Bz * Tz * Dz;    // [B, L]
    float* out_dur    = out_dpo + (size_t)Bz * Lz;            // [B, L]

    int8_t *xa0, *xa1, *h1a0, *h1a1, *w1b0, *w1b1, *w2b0, *w2b1;
    float *glw, *scal;
    cudaGetSymbolAddress((void**)&xa0,  g_xa0);
    cudaGetSymbolAddress((void**)&xa1,  g_xa1);
    cudaGetSymbolAddress((void**)&h1a0, g_h1a0);
    cudaGetSymbolAddress((void**)&h1a1, g_h1a1);
    cudaGetSymbolAddress((void**)&w1b0, g_w1b0);
    cudaGetSymbolAddress((void**)&w1b1, g_w1b1);
    cudaGetSymbolAddress((void**)&w2b0, g_w2b0);
    cudaGetSymbolAddress((void**)&w2b1, g_w2b1);
    cudaGetSymbolAddress((void**)&glw,  g_glw);
    cudaGetSymbolAddress((void**)&scal, g_scal);

    cudaFuncSetAttribute(fused_all, cudaFuncAttributeMaxDynamicSharedMemorySize, CONV_SMEM);

    // Prep: x quantize/split | weight quantize/split (ALL 3 taps) | scalars
    prep_all<<<PREP_TOTAL, 256>>>(x, xa0, xa1, conv1_w, conv2_w,
                                  w1b0, w1b1, w2b0, w2b1,
                                  ln2_g, ln2_b, lin_w, lin_b, glw, scal);

    // One fused pipeline kernel
    fused_all<<<BLK_TOTAL, 512, CONV_SMEM>>>(
        xa0, xa1, h1a0, h1a1,
        w1b0, w1b1, w2b0, w2b1,
        conv1_b, ln1_g, ln1_b, conv2_b, ln2_g, ln2_b,
        glw, scal, target, x, out_gather, out_dpo, out_dur);
}

// round 14
// speedup vs baseline: 3.5332x; 3.5332x over previous
#include <cuda_runtime.h>
#include <cuda_fp16.h>
#include <math.h>
#include <stdint.h>

#define Bz 32
#define Lz 768
#define Dz 256
#define Fz 256
#define Tz 3072

#define NCONV 384                       // conv tile CTAs per layer (M=64)
// fused grid block ranges
#define BLK_CS   NCONV                  // 32 cumsum
#define BLK_C2   (BLK_CS + Bz)          // 384 conv2 tiles
#define BLK_GA   (BLK_C2 + NCONV)      // 1536 gather
#define BLK_TOTAL (BLK_GA + 48 * Bz)    // 2336

// prep_all dispatch ranges
#define PREP_X_BLOCKS 3072              // 6,291,456 / 2048
#define PREP_W_BLOCKS 768               // 2 tensors x 98,304 / 256 (k-pair u32)
#define PREP_TOTAL (PREP_X_BLOCKS + PREP_W_BLOCKS + 1)

#define NFLAGS (NCONV + Bz)

// ---------------------------------------------------------------------------
// Scratch (allocation-free: __device__ globals)
// ---------------------------------------------------------------------------
__device__ __half g_xh[Bz * Lz * Dz];          // x in fp16
__device__ __half g_h1[Bz * Lz * Fz];          // LN1 output in fp16
// weights: [tap][cout][pair] u32, pair = (fp16 cin=2p, cin=2p+1)
__device__ uint32_t g_w1p[3 * 256 * 128];
__device__ uint32_t g_w2p[3 * 256 * 128];
__device__ float  g_glw[256];
__device__ float  g_scal[2];
__device__ int    g_cum[Bz * Lz];
__device__ int    g_flag[NFLAGS];

// ---------------------------------------------------------------------------
// helpers
// ---------------------------------------------------------------------------
__device__ __forceinline__ uint32_t smem_u32(const void* p) {
    uint32_t a;
    asm("{ .reg .u64 t; cvta.to.shared.u64 t, %1; cvt.u32.u64 %0, t; }"
        : "=r"(a) : "l"(p));
    return a;
}

__device__ __forceinline__ void cp16(uint32_t dst, const void* src, int src_bytes) {
    asm volatile("cp.async.cg.shared.global [%0], [%1], 16, %2;"
                 :: "r"(dst), "l"(src), "r"(src_bytes) : "memory");
}
#define CP_COMMIT() asm volatile("cp.async.commit_group;" ::: "memory")
#define CP_WAIT(n)  asm volatile("cp.async.wait_group %0;" :: "n"(n) : "memory")

#define LDSM_X4(r, addr) \
    asm volatile("ldmatrix.sync.aligned.m8n8.x4.shared.b16 {%0,%1,%2,%3}, [%4];" \
        : "=r"((r)[0]), "=r"((r)[1]), "=r"((r)[2]), "=r"((r)[3]) : "r"(addr))

// fp16 MMA m16n8k16, fp32 accumulate (non-volatile: let ptxas schedule)
__device__ __forceinline__ void mma16816(float* c, const uint32_t* a,
                                         uint32_t b0, uint32_t b1)
{
    asm("mma.sync.aligned.m16n8k16.row.col.f32.f16.f16.f32 "
        "{%0,%1,%2,%3}, {%4,%5,%6,%7}, {%8,%9}, {%0,%1,%2,%3};\n"
        : "+f"(c[0]), "+f"(c[1]), "+f"(c[2]), "+f"(c[3])
        : "r"(a[0]), "r"(a[1]), "r"(a[2]), "r"(a[3]), "r"(b0), "r"(b1));
}

__device__ __forceinline__ void flag_publish(int idx) {
    __threadfence();
    if (threadIdx.x == 0) atomicExch(&g_flag[idx], 1);
}
__device__ __forceinline__ void flag_spin(int idx) {
    if (threadIdx.x == 0) {
        while (atomicAdd(&g_flag[idx], 0) == 0) __nanosleep(64);
    }
}

// ---------------------------------------------------------------------------
// Unified prep kernel (256 threads/block):
//   blk < 3072          : x fp32 -> fp16 (8 elems/thread)
//   3072 <= blk < 3840  : weights -> [tap][cout][pair] fp16-pair u32
//   blk == 3840         : glw/scal scalars + flag reset
// ---------------------------------------------------------------------------
__global__ __launch_bounds__(256)
void prep_all(const float* __restrict__ x, __half* __restrict__ xh,
              const float* __restrict__ w1, const float* __restrict__ w2,
              uint32_t* __restrict__ p1, uint32_t* __restrict__ p2,
              const float* __restrict__ g, const float* __restrict__ bb,
              const float* __restrict__ lw, const float* __restrict__ lb,
              float* __restrict__ glw, float* __restrict__ scal)
{
    const int blk = blockIdx.x;
    const int t = threadIdx.x;

    if (blk < PREP_X_BLOCKS) {
        size_t i = ((size_t)blk * 256 + t) * 8;
        float4 f0 = *(const float4*)(x + i);
        float4 f1 = *(const float4*)(x + i + 4);
        __half2 h0 = __floats2half2_rn(f0.x, f0.y);
        __half2 h1 = __floats2half2_rn(f0.z, f0.w);
        __half2 h2 = __floats2half2_rn(f1.x, f1.y);
        __half2 h3 = __floats2half2_rn(f1.z, f1.w);
        uint4 v;
        v.x = *(uint32_t*)&h0; v.y = *(uint32_t*)&h1;
        v.z = *(uint32_t*)&h2; v.w = *(uint32_t*)&h3;
        *(uint4*)(xh + i) = v;
        return;
    }
    if (blk < PREP_X_BLOCKS + PREP_W_BLOCKS) {
        int e = blk - PREP_X_BLOCKS;                   // 0..767
        int sel = e >= 384;
        int idx = (e - sel * 384) * 256 + t;           // 0 .. 98303
        const float* w = sel ? w2 : w1;
        uint32_t* wp = sel ? p2 : p1;
        int p   = idx & 127;
        int n   = (idx >> 7) & 255;
        int tap = idx >> 15;
        float a = w[((size_t)(tap * 256 + 2 * p))     * 256 + n];
        float b = w[((size_t)(tap * 256 + 2 * p + 1)) * 256 + n];
        __half2 pk = __floats2half2_rn(a, b);
        wp[idx] = *(uint32_t*)&pk;
        return;
    }
    // scalars + flag reset
    {
        for (int i = t; i < NFLAGS; i += 256) g_flag[i] = 0;
        __shared__ float sg[8], sb[8];
        float lwv = lw[t];
        float gv = g[t] * lwv;
        float bv = bb[t] * lwv;
        glw[t] = gv;
#pragma unroll
        for (int o = 16; o; o >>= 1) {
            gv += __shfl_xor_sync(0xffffffffu, gv, o);
            bv += __shfl_xor_sync(0xffffffffu, bv, o);
        }
        if ((t & 31) == 0) { sg[t >> 5] = gv; sb[t >> 5] = bv; }
        __syncthreads();
        if (t == 0) {
            float G = 0.f, Bv = 0.f;
            for (int i = 0; i < 8; i++) { G += sg[i]; Bv += sb[i]; }
            scal[0] = G;
            scal[1] = Bv + lb[0];
        }
    }
}

// ---------------------------------------------------------------------------
// cumsum for one batch (256 threads, 3 elems each)
// ---------------------------------------------------------------------------
__device__ void cumsum_block(int b, const int* __restrict__ target,
                             float* __restrict__ dpo_out, char* smem)
{
    int* ps = (int*)smem;
    const int t = threadIdx.x;
    const size_t base = (size_t)b * Lz + 3 * t;
    int v0 = target[base], v1 = target[base + 1], v2 = target[base + 2];
    int s1 = v0 + v1, s2 = s1 + v2;
    ps[t] = s2;
    __syncthreads();
#pragma unroll
    for (int off = 1; off < 256; off <<= 1) {
        int u = (t >= off) ? ps[t - off] : 0;
        __syncthreads();
        ps[t] += u;
        __syncthreads();
    }
    int pre = (t > 0) ? ps[t - 1] : 0;
    g_cum[base]     = pre + v0;
    g_cum[base + 1] = pre + s1;
    g_cum[base + 2] = pre + s2;
    dpo_out[base]     = (float)v0;
    dpo_out[base + 1] = (float)v1;
    dpo_out[base + 2] = (float)v2;
    __syncthreads();
    flag_publish(NCONV + b);
}

// ---------------------------------------------------------------------------
// gather for one (batch, 64-t block): e in 0..1535
// ---------------------------------------------------------------------------
__device__ void gather_block(int e, const float* __restrict__ x,
                             float* __restrict__ dout, char* smem)
{
    int* cum = (int*)smem;
    const int b = e / 48;
    const int tpart = e % 48;
    const int tid = threadIdx.x;

    flag_spin(NCONV + b);
    __syncthreads();

    for (int i = tid; i < Lz; i += 256)
        cum[i] = g_cum[(size_t)b * Lz + i];
    __syncthreads();

    const int total = cum[Lz - 1];
    const int t0 = tpart * 64;
    const int sub  = tid & 63;
    const int tloc = tid >> 6;

    const float4* xrow = (const float4*)(x + (size_t)b * Lz * Dz);
    float4* orow = (float4*)(dout + (size_t)b * Tz * Dz);

#pragma unroll 4
    for (int it = 0; it < 16; ++it) {
        int t = t0 + it * 4 + tloc;
        int lo = 0, hi = Lz;
        while (lo < hi) {
            int mid = (lo + hi) >> 1;
            if (cum[mid] <= t) lo = mid + 1; else hi = mid;
        }
        float4 v;
        if (t < total) {
            int idx = min(lo, Lz - 1);
            v = xrow[(size_t)idx * 64 + sub];
        } else {
            v = make_float4(0.0f, 0.0f, 0.0f, 0.0f);
        }
        orow[(size_t)t * 64 + sub] = v;
    }
}

// ---------------------------------------------------------------------------
// conv tile: M=64 x N=256, 256 threads (8 warps 2M x 4N), fp16 single-pass,
// 3-stage cp.async pipeline (one barrier per chunk), 24 chunks of K=32.
// Stage: A 64 rows x 32 fp16 stride-40 (5120B) + B 256 n x 16 pairs stride-20
// (20480B) = 25600B. 2 CTAs/SM.
// ---------------------------------------------------------------------------
#define SA 0
#define SB 5120
#define STAGE 25600
#define STAGE0_OFF 4096
#define CONV_SMEM (STAGE0_OFF + 3 * STAGE)   // 80896

__device__ __forceinline__ void load_chunk(
    uint32_t stg, int c, int tid, int l0, size_t rowbase,
    const __half* __restrict__ Ah, const uint32_t* __restrict__ Wp)
{
    const int tap  = c >> 3;
    const int cin0 = (c & 7) << 5;
    // A: 64 rows x 64B (4 segs of 16B); one (row,seg) per thread
    {
        int row = tid >> 2, seg = tid & 3;
        int gl = l0 + row + tap - 1;
        int ok = (gl >= 0 && gl < Lz) ? 16 : 0;
        int glc = gl < 0 ? 0 : (gl >= Lz ? Lz - 1 : gl);
        size_t off = ((rowbase + glc) << 8) + cin0 + (seg << 3);
        cp16(stg + SA + row * 80 + seg * 16, Ah + off, ok);
    }
    // B: 256 n x 16 pairs u32 (4 segs of 16B per n) = 1024 jobs, 4 per thread
    const int p0 = (c & 7) << 4;
    const uint32_t* bsrc = Wp + (size_t)tap * 256 * 128 + p0;
#pragma unroll
    for (int i = 0; i < 4; ++i) {
        int idx = tid + (i << 8);
        int n = idx >> 2, seg = idx & 3;
        cp16(stg + SB + n * 80 + seg * 16, bsrc + n * 128 + seg * 4, 16);
    }
}

__device__ void conv_tile(
    int tile, bool fin, char* smem,
    const __half* __restrict__ Ah, const uint32_t* __restrict__ Wp,
    const float* __restrict__ bias, const float* __restrict__ gamma,
    const float* __restrict__ beta, const float* __restrict__ glw,
    const float* __restrict__ scal,
    __half* __restrict__ outh, float* __restrict__ dur)
{
    const uint32_t sb = smem_u32(smem);
    float* svec = (float*)smem;                       // [4][256]
    const uint32_t stage0 = sb + STAGE0_OFF;

    const int tid = threadIdx.x;
    const int wid = tid >> 5, lane = tid & 31;
    const int wm = wid >> 2, wn = wid & 3;            // 2M x 4N warps
    const int grp = lane >> 2, tig = lane & 3;

    const int batch = tile / 12;
    const int part  = tile % 12;
    const int l0 = part * 64;
    const size_t rowbase = (size_t)batch * Lz;

    if (fin) {
        flag_spin(tile);
        if (part > 0)  flag_spin(tile - 1);
        if (part < 11) flag_spin(tile + 1);
        __threadfence();
    }
    __syncthreads();

    svec[tid]       = bias[tid];
    svec[256 + tid] = gamma[tid];
    svec[512 + tid] = beta[tid];
    svec[768 + tid] = fin ? glw[tid] : 0.f;

    // ldmatrix per-lane byte offsets (within a stage)
    const uint32_t a_off = (uint32_t)((wm * 32 + (lane & 15)) * 80 + (lane >> 4) * 16);
    const uint32_t b_row = (uint32_t)(wn * 64 + ((lane & 7) | ((lane >> 4) << 3)));
    const uint32_t b_off = b_row * 80 + (((lane >> 3) & 1) * 16);

    float acc[2][8][4];
#pragma unroll
    for (int mt = 0; mt < 2; mt++)
#pragma unroll
        for (int nt = 0; nt < 8; nt++)
#pragma unroll
            for (int i = 0; i < 4; i++) acc[mt][nt][i] = 0.f;

    load_chunk(stage0,         0, tid, l0, rowbase, Ah, Wp);
    CP_COMMIT();
    load_chunk(stage0 + STAGE, 1, tid, l0, rowbase, Ah, Wp);
    CP_COMMIT();

    int stg_idx = 0;
    for (int c = 0; c < 24; ++c) {
        const uint32_t stg = stage0 + stg_idx * STAGE;
        if (c < 23) CP_WAIT(1); else CP_WAIT(0);
        __syncthreads();

        // issue loads for c+2 right away (lands while computing c, c+1)
        if (c + 2 < 24) {
            int nidx = stg_idx + 2; if (nidx >= 3) nidx -= 3;
            load_chunk(stage0 + nidx * STAGE, c + 2, tid, l0, rowbase, Ah, Wp);
            CP_COMMIT();
        }

#pragma unroll
        for (int kt = 0; kt < 2; ++kt) {
            uint32_t ah[2][4];
#pragma unroll
            for (int mt = 0; mt < 2; ++mt)
                LDSM_X4(ah[mt], stg + SA + a_off + mt * (16 * 80) + kt * 32);
#pragma unroll
            for (int j = 0; j < 4; ++j) {          // covers nt = 2j, 2j+1
                uint32_t bh[4];
                LDSM_X4(bh, stg + SB + b_off + j * (16 * 80) + kt * 32);
#pragma unroll
                for (int h = 0; h < 2; ++h)
#pragma unroll
                    for (int mt = 0; mt < 2; ++mt)
                        mma16816(acc[mt][j * 2 + h], ah[mt], bh[h * 2], bh[h * 2 + 1]);
            }
        }
        if (++stg_idx == 3) stg_idx = 0;
    }
    __syncthreads();   // stage region free -> epilogue overlay

    // ----- epilogue -----
    float* pa  = (float*)(smem + STAGE0_OFF);     // [3][64][4]
    float* smu = pa + 3 * 64 * 4;                 // [64]
    float* srs = smu + 64;                        // [64]

#pragma unroll
    for (int mt = 0; mt < 2; ++mt)
#pragma unroll
        for (int hf = 0; hf < 2; ++hf) {
            float s = 0.f, sq = 0.f, sd = 0.f;
#pragma unroll
            for (int nt = 0; nt < 8; ++nt) {
                int col = wn * 64 + nt * 8 + 2 * tig;
                float v0 = fmaxf(acc[mt][nt][hf * 2 + 0] + svec[col], 0.f);
                float v1 = fmaxf(acc[mt][nt][hf * 2 + 1] + svec[col + 1], 0.f);
                acc[mt][nt][hf * 2 + 0] = v0;
                acc[mt][nt][hf * 2 + 1] = v1;
                s += v0 + v1;
                sq += v0 * v0 + v1 * v1;
                if (fin) sd += v0 * svec[768 + col] + v1 * svec[768 + col + 1];
            }
            s  += __shfl_xor_sync(0xffffffffu, s, 1);
            s  += __shfl_xor_sync(0xffffffffu, s, 2);
            sq += __shfl_xor_sync(0xffffffffu, sq, 1);
            sq += __shfl_xor_sync(0xffffffffu, sq, 2);
            if (fin) {
                sd += __shfl_xor_sync(0xffffffffu, sd, 1);
                sd += __shfl_xor_sync(0xffffffffu, sd, 2);
            }
            if (tig == 0) {
                int row = wm * 32 + mt * 16 + hf * 8 + grp;
                pa[0 * 256 + row * 4 + wn] = s;
                pa[1 * 256 + row * 4 + wn] = sq;
                if (fin) pa[2 * 256 + row * 4 + wn] = sd;
            }
        }
    __syncthreads();

    if (tid < 64) {
        int row = tid;
        float s  = pa[row * 4] + pa[row * 4 + 1] + pa[row * 4 + 2] + pa[row * 4 + 3];
        float sq = pa[256 + row * 4] + pa[256 + row * 4 + 1] +
                   pa[256 + row * 4 + 2] + pa[256 + row * 4 + 3];
        float mu  = s * (1.f / 256.f);
        float var = sq * (1.f / 256.f) - mu * mu;
        float rs  = rsqrtf(var + 1e-5f);
        if (fin) {
            float s3 = pa[512 + row * 4] + pa[512 + row * 4 + 1] +
                       pa[512 + row * 4 + 2] + pa[512 + row * 4 + 3];
            dur[(size_t)tile * 64 + row] = expf(rs * (s3 - mu * scal[0]) + scal[1]);
        } else {
            smu[row] = mu;
            srs[row] = rs;
        }
    }

    if (!fin) {
        __syncthreads();
#pragma unroll
        for (int mt = 0; mt < 2; ++mt)
#pragma unroll
            for (int hf = 0; hf < 2; ++hf) {
                int row = wm * 32 + mt * 16 + hf * 8 + grp;
                float mu = smu[row], rs = srs[row];
#pragma unroll
                for (int nt = 0; nt < 8; ++nt) {
                    int col = wn * 64 + nt * 8 + 2 * tig;
                    float v0 = (acc[mt][nt][hf * 2 + 0] - mu) * rs * svec[256 + col]     + svec[512 + col];
                    float v1 = (acc[mt][nt][hf * 2 + 1] - mu) * rs * svec[256 + col + 1] + svec[512 + col + 1];
                    __half2 pk = __floats2half2_rn(v0, v1);
                    *(uint32_t*)(outh + ((size_t)tile * 64 + row) * 256 + col) = *(uint32_t*)&pk;
                }
            }
        __syncthreads();   // all h1 writes done before publish
        flag_publish(tile);
    }
}

// ---------------------------------------------------------------------------
// Fused pipeline kernel: conv1 | cumsum | conv2(+lin+exp) | gather
// ---------------------------------------------------------------------------
__global__ void __launch_bounds__(256, 2)
fused_all(const __half* __restrict__ xh, __half* __restrict__ h1,
          const uint32_t* __restrict__ w1p, const uint32_t* __restrict__ w2p,
          const float* __restrict__ conv1_b, const float* __restrict__ ln1_g,
          const float* __restrict__ ln1_b,
          const float* __restrict__ conv2_b, const float* __restrict__ ln2_g,
          const float* __restrict__ ln2_b,
          const float* __restrict__ glw, const float* __restrict__ scal,
          const int* __restrict__ target, const float* __restrict__ x,
          float* __restrict__ out_gather, float* __restrict__ out_dpo,
          float* __restrict__ out_dur)
{
    extern __shared__ char smem[];
    const int blk = blockIdx.x;

    if (blk < BLK_CS) {
        conv_tile(blk, false, smem, xh, w1p,
                  conv1_b, ln1_g, ln1_b, glw, scal, h1, nullptr);
    } else if (blk < BLK_C2) {
        cumsum_block(blk - BLK_CS, target, out_dpo, smem);
    } else if (blk < BLK_GA) {
        conv_tile(blk - BLK_C2, true, smem, h1, w2p,
                  conv2_b, ln2_g, ln2_b, glw, scal, nullptr, out_dur);
    } else {
        gather_block(blk - BLK_GA, x, out_gather, smem);
    }
}

// ---------------------------------------------------------------------------
// Launch
// ---------------------------------------------------------------------------
extern "C" void kernel_launch(void* const* d_in, const int* in_sizes, int n_in,
                              void* d_out, int out_size)
{
    const float* x       = (const float*)d_in[0];
    const int*   target  = (const int*)  d_in[1];
    const float* conv1_w = (const float*)d_in[3];
    const float* conv1_b = (const float*)d_in[4];
    const float* ln1_g   = (const float*)d_in[5];
    const float* ln1_b   = (const float*)d_in[6];
    const float* conv2_w = (const float*)d_in[7];
    const float* conv2_b = (const float*)d_in[8];
    const float* ln2_g   = (const float*)d_in[9];
    const float* ln2_b   = (const float*)d_in[10];
    const float* lin_w   = (const float*)d_in[11];
    const float* lin_b   = (const float*)d_in[12];

    float* out_gather = (float*)d_out;                        // [B, T, D]
    float* out_dpo    = out_gather + (size_t)Bz * Tz * Dz;    // [B, L]
    float* out_dur    = out_dpo + (size_t)Bz * Lz;            // [B, L]

    __half *xh, *h1;
    uint32_t *w1p, *w2p;
    float *glw, *scal;
    cudaGetSymbolAddress((void**)&xh,  g_xh);
    cudaGetSymbolAddress((void**)&h1,  g_h1);
    cudaGetSymbolAddress((void**)&w1p, g_w1p);
    cudaGetSymbolAddress((void**)&w2p, g_w2p);
    cudaGetSymbolAddress((void**)&glw, g_glw);
    cudaGetSymbolAddress((void**)&scal, g_scal);

    cudaFuncSetAttribute(fused_all, cudaFuncAttributeMaxDynamicSharedMemorySize, CONV_SMEM);

    // Prep: x -> fp16 | weights -> fp16 k-pair u32 | scalars + flag reset
    prep_all<<<PREP_TOTAL, 256>>>(x, xh, conv1_w, conv2_w, w1p, w2p,
                                  ln2_g, ln2_b, lin_w, lin_b, glw, scal);

    // One fused pipeline kernel
    fused_all<<<BLK_TOTAL, 256, CONV_SMEM>>>(
        xh, h1, w1p, w2p,
        conv1_b, ln1_g, ln1_b, conv2_b, ln2_g, ln2_b,
        glw, scal, target, x, out_gather, out_dpo, out_dur);
}

// round 15
// speedup vs baseline: 4.0055x; 1.1337x over previous
#include <cuda_runtime.h>
#include <cuda_fp16.h>
#include <math.h>
#include <stdint.h>

#define Bz 32
#define Lz 768
#define Dz 256
#define Fz 256
#define Tz 3072

#define NCONV 384                       // conv tile CTAs per layer (M=64)
// fused grid block ranges
#define BLK_CS   NCONV                  // 32 cumsum
#define BLK_C2   (BLK_CS + Bz)          // 384 conv2 tiles
#define BLK_GA   (BLK_C2 + NCONV)       // 1536 gather
#define BLK_TOTAL (BLK_GA + 48 * Bz)    // 2336

// prep_all dispatch ranges
#define PREP_X_BLOCKS 3072              // 6,291,456 / 2048
#define PREP_W_BLOCKS 768               // 2 layers x 98,304 u32 / 256
#define PREP_TOTAL (PREP_X_BLOCKS + PREP_W_BLOCKS + 1)

#define NFLAGS (NCONV + Bz)

#define B_CHUNK_BYTES 20480             // 256 rows x 80B (pads included)
#define B_CHUNK_U32   5120

// ---------------------------------------------------------------------------
// Scratch (allocation-free: __device__ globals)
// ---------------------------------------------------------------------------
__device__ __half g_xh[Bz * Lz * Dz];          // x in fp16
__device__ __half g_h1[Bz * Lz * Fz];          // LN1 output in fp16
// weight images: exact smem stage layout per chunk (24 x 256rows x 80B)
__device__ uint32_t g_wimg1[24 * B_CHUNK_U32];
__device__ uint32_t g_wimg2[24 * B_CHUNK_U32];
__device__ float  g_glw[256];
__device__ float  g_scal[2];
__device__ int    g_cum[Bz * Lz];
__device__ int    g_flag[NFLAGS];

// ---------------------------------------------------------------------------
// helpers
// ---------------------------------------------------------------------------
__device__ __forceinline__ uint32_t smem_u32(const void* p) {
    uint32_t a;
    asm("{ .reg .u64 t; cvta.to.shared.u64 t, %1; cvt.u32.u64 %0, t; }"
        : "=r"(a) : "l"(p));
    return a;
}

__device__ __forceinline__ void cp16(uint32_t dst, const void* src, int src_bytes) {
    asm volatile("cp.async.cg.shared.global [%0], [%1], 16, %2;"
                 :: "r"(dst), "l"(src), "r"(src_bytes) : "memory");
}
#define CP_COMMIT() asm volatile("cp.async.commit_group;" ::: "memory")
#define CP_WAIT(n)  asm volatile("cp.async.wait_group %0;" :: "n"(n) : "memory")

// sm_90 bulk copy: one instruction per 20KB B tile, completes via mbarrier
#define CP_BULK(dst, src, bytes, mbar) \
    asm volatile("cp.async.bulk.shared::cta.global.mbarrier::complete_tx::bytes " \
                 "[%0], [%1], %2, [%3];" \
                 :: "r"(dst), "l"(src), "r"((uint32_t)(bytes)), "r"(mbar) : "memory")
#define MBAR_INIT(mbar, cnt) \
    asm volatile("mbarrier.init.shared.b64 [%0], %1;" :: "r"(mbar), "r"((uint32_t)(cnt)) : "memory")
#define MBAR_EXPECT(mbar, bytes) \
    asm volatile("mbarrier.arrive.expect_tx.shared.b64 _, [%0], %1;" \
                 :: "r"(mbar), "r"((uint32_t)(bytes)) : "memory")
#define MBAR_WAIT(mbar, parity) do { \
    uint32_t _m = (mbar), _p = (parity), _done; \
    asm volatile("{\n\t.reg .pred p;\n\t" \
        "mbarrier.try_wait.parity.acquire.cta.shared::cta.b64 p, [%1], %2;\n\t" \
        "selp.b32 %0, 1, 0, p;\n\t}" : "=r"(_done) : "r"(_m), "r"(_p) : "memory"); \
    if (!_done) { \
        asm volatile("{\n\t.reg .pred P1;\n\t" \
            "WAIT_LOOP_%=:\n\t" \
            "mbarrier.try_wait.parity.acquire.cta.shared::cta.b64 P1, [%0], %1, 0x989680;\n\t" \
            "@P1 bra.uni WAIT_DONE_%=;\n\t" \
            "bra.uni WAIT_LOOP_%=;\n\t" \
            "WAIT_DONE_%=:\n\t}" :: "r"(_m), "r"(_p) : "memory"); \
    } \
} while (0)

#define LDSM_X4(r, addr) \
    asm volatile("ldmatrix.sync.aligned.m8n8.x4.shared.b16 {%0,%1,%2,%3}, [%4];" \
        : "=r"((r)[0]), "=r"((r)[1]), "=r"((r)[2]), "=r"((r)[3]) : "r"(addr))

// fp16 MMA m16n8k16, fp32 accumulate (non-volatile: let ptxas schedule)
__device__ __forceinline__ void mma16816(float* c, const uint32_t* a,
                                         uint32_t b0, uint32_t b1)
{
    asm("mma.sync.aligned.m16n8k16.row.col.f32.f16.f16.f32 "
        "{%0,%1,%2,%3}, {%4,%5,%6,%7}, {%8,%9}, {%0,%1,%2,%3};\n"
        : "+f"(c[0]), "+f"(c[1]), "+f"(c[2]), "+f"(c[3])
        : "r"(a[0]), "r"(a[1]), "r"(a[2]), "r"(a[3]), "r"(b0), "r"(b1));
}

__device__ __forceinline__ void flag_publish(int idx) {
    __threadfence();
    if (threadIdx.x == 0) atomicExch(&g_flag[idx], 1);
}
__device__ __forceinline__ void flag_spin(int idx) {
    if (threadIdx.x == 0) {
        while (atomicAdd(&g_flag[idx], 0) == 0) __nanosleep(64);
    }
}

// ---------------------------------------------------------------------------
// Unified prep kernel (256 threads/block):
//   blk < 3072          : x fp32 -> fp16 (8 elems/thread)
//   3072 <= blk < 3840  : weights -> chunk-image layout (u32 fp16-pairs)
//   blk == 3840         : glw/scal scalars + flag reset
// ---------------------------------------------------------------------------
__global__ __launch_bounds__(256)
void prep_all(const float* __restrict__ x, __half* __restrict__ xh,
              const float* __restrict__ w1, const float* __restrict__ w2,
              uint32_t* __restrict__ img1, uint32_t* __restrict__ img2,
              const float* __restrict__ g, const float* __restrict__ bb,
              const float* __restrict__ lw, const float* __restrict__ lb,
              float* __restrict__ glw, float* __restrict__ scal)
{
    const int blk = blockIdx.x;
    const int t = threadIdx.x;

    if (blk < PREP_X_BLOCKS) {
        size_t i = ((size_t)blk * 256 + t) * 8;
        float4 f0 = *(const float4*)(x + i);
        float4 f1 = *(const float4*)(x + i + 4);
        __half2 h0 = __floats2half2_rn(f0.x, f0.y);
        __half2 h1 = __floats2half2_rn(f0.z, f0.w);
        __half2 h2 = __floats2half2_rn(f1.x, f1.y);
        __half2 h3 = __floats2half2_rn(f1.z, f1.w);
        uint4 v;
        v.x = *(uint32_t*)&h0; v.y = *(uint32_t*)&h1;
        v.z = *(uint32_t*)&h2; v.w = *(uint32_t*)&h3;
        *(uint4*)(xh + i) = v;
        return;
    }
    if (blk < PREP_X_BLOCKS + PREP_W_BLOCKS) {
        int e = blk - PREP_X_BLOCKS;                   // 0..767
        int sel = e >= 384;
        int idx = (e - sel * 384) * 256 + t;           // 0 .. 98303
        const float* w = sel ? w2 : w1;
        uint32_t* img = sel ? img2 : img1;
        int c   = idx >> 12;                            // chunk 0..23
        int rem = idx & 4095;
        int n   = rem >> 4;                             // cout 0..255
        int q   = rem & 15;                             // pair-in-chunk 0..15
        int tap = c >> 3;
        int p   = ((c & 7) << 4) + q;                   // cin pair 0..127
        float a = w[((size_t)(tap * 256 + 2 * p))     * 256 + n];
        float b = w[((size_t)(tap * 256 + 2 * p + 1)) * 256 + n];
        __half2 pk = __floats2half2_rn(a, b);
        img[c * B_CHUNK_U32 + n * 20 + q] = *(uint32_t*)&pk;
        return;
    }
    // scalars + flag reset
    {
        for (int i = t; i < NFLAGS; i += 256) g_flag[i] = 0;
        __shared__ float sg[8], sb[8];
        float lwv = lw[t];
        float gv = g[t] * lwv;
        float bv = bb[t] * lwv;
        glw[t] = gv;
#pragma unroll
        for (int o = 16; o; o >>= 1) {
            gv += __shfl_xor_sync(0xffffffffu, gv, o);
            bv += __shfl_xor_sync(0xffffffffu, bv, o);
        }
        if ((t & 31) == 0) { sg[t >> 5] = gv; sb[t >> 5] = bv; }
        __syncthreads();
        if (t == 0) {
            float G = 0.f, Bv = 0.f;
            for (int i = 0; i < 8; i++) { G += sg[i]; Bv += sb[i]; }
            scal[0] = G;
            scal[1] = Bv + lb[0];
        }
    }
}

// ---------------------------------------------------------------------------
// cumsum for one batch (256 threads, 3 elems each)
// ---------------------------------------------------------------------------
__device__ void cumsum_block(int b, const int* __restrict__ target,
                             float* __restrict__ dpo_out, char* smem)
{
    int* ps = (int*)smem;
    const int t = threadIdx.x;
    const size_t base = (size_t)b * Lz + 3 * t;
    int v0 = target[base], v1 = target[base + 1], v2 = target[base + 2];
    int s1 = v0 + v1, s2 = s1 + v2;
    ps[t] = s2;
    __syncthreads();
#pragma unroll
    for (int off = 1; off < 256; off <<= 1) {
        int u = (t >= off) ? ps[t - off] : 0;
        __syncthreads();
        ps[t] += u;
        __syncthreads();
    }
    int pre = (t > 0) ? ps[t - 1] : 0;
    g_cum[base]     = pre + v0;
    g_cum[base + 1] = pre + s1;
    g_cum[base + 2] = pre + s2;
    dpo_out[base]     = (float)v0;
    dpo_out[base + 1] = (float)v1;
    dpo_out[base + 2] = (float)v2;
    __syncthreads();
    flag_publish(NCONV + b);
}

// ---------------------------------------------------------------------------
// gather for one (batch, 64-t block): e in 0..1535
// ---------------------------------------------------------------------------
__device__ void gather_block(int e, const float* __restrict__ x,
                             float* __restrict__ dout, char* smem)
{
    int* cum = (int*)smem;
    const int b = e / 48;
    const int tpart = e % 48;
    const int tid = threadIdx.x;

    flag_spin(NCONV + b);
    __syncthreads();

    for (int i = tid; i < Lz; i += 256)
        cum[i] = g_cum[(size_t)b * Lz + i];
    __syncthreads();

    const int total = cum[Lz - 1];
    const int t0 = tpart * 64;
    const int sub  = tid & 63;
    const int tloc = tid >> 6;

    const float4* xrow = (const float4*)(x + (size_t)b * Lz * Dz);
    float4* orow = (float4*)(dout + (size_t)b * Tz * Dz);

#pragma unroll 4
    for (int it = 0; it < 16; ++it) {
        int t = t0 + it * 4 + tloc;
        int lo = 0, hi = Lz;
        while (lo < hi) {
            int mid = (lo + hi) >> 1;
            if (cum[mid] <= t) lo = mid + 1; else hi = mid;
        }
        float4 v;
        if (t < total) {
            int idx = min(lo, Lz - 1);
            v = xrow[(size_t)idx * 64 + sub];
        } else {
            v = make_float4(0.0f, 0.0f, 0.0f, 0.0f);
        }
        orow[(size_t)t * 64 + sub] = v;
    }
}

// ---------------------------------------------------------------------------
// conv tile: M=64 x N=256, 256 threads (8 warps 2M x 4N), fp16 single-pass,
// 3-stage pipeline. A via cp.async (1 op/thread/chunk); B via ONE bulk copy
// per chunk (mbarrier complete_tx). 24 chunks of K=32. 2 CTAs/SM.
// ---------------------------------------------------------------------------
#define SA 0
#define SB 5120
#define STAGE 25600
#define MBAR_OFF 4096                    // 3 x 8B mbarriers
#define STAGE0_OFF 4224
#define CONV_SMEM (STAGE0_OFF + 3 * STAGE)   // 81024

__device__ __forceinline__ void load_A(
    uint32_t stg, int c, int tid, int l0, size_t rowbase,
    const __half* __restrict__ Ah)
{
    const int tap  = c >> 3;
    const int cin0 = (c & 7) << 5;
    int row = tid >> 2, seg = tid & 3;
    int gl = l0 + row + tap - 1;
    int ok = (gl >= 0 && gl < Lz) ? 16 : 0;
    int glc = gl < 0 ? 0 : (gl >= Lz ? Lz - 1 : gl);
    size_t off = ((rowbase + glc) << 8) + cin0 + (seg << 3);
    cp16(stg + SA + row * 80 + seg * 16, Ah + off, ok);
}

__device__ void conv_tile(
    int tile, bool fin, char* smem,
    const __half* __restrict__ Ah, const uint32_t* __restrict__ Wimg,
    const float* __restrict__ bias, const float* __restrict__ gamma,
    const float* __restrict__ beta, const float* __restrict__ glw,
    const float* __restrict__ scal,
    __half* __restrict__ outh, float* __restrict__ dur)
{
    const uint32_t sb = smem_u32(smem);
    float* svec = (float*)smem;                       // [4][256]
    const uint32_t mbar0  = sb + MBAR_OFF;
    const uint32_t stage0 = sb + STAGE0_OFF;

    const int tid = threadIdx.x;
    const int wid = tid >> 5, lane = tid & 31;
    const int wm = wid >> 2, wn = wid & 3;            // 2M x 4N warps
    const int grp = lane >> 2, tig = lane & 3;

    const int batch = tile / 12;
    const int part  = tile % 12;
    const int l0 = part * 64;
    const size_t rowbase = (size_t)batch * Lz;

    if (tid == 0) {
        MBAR_INIT(mbar0,      1);
        MBAR_INIT(mbar0 + 8,  1);
        MBAR_INIT(mbar0 + 16, 1);
    }
    if (fin) {
        flag_spin(tile);
        if (part > 0)  flag_spin(tile - 1);
        if (part < 11) flag_spin(tile + 1);
        __threadfence();
    }
    __syncthreads();

    svec[tid]       = bias[tid];
    svec[256 + tid] = gamma[tid];
    svec[512 + tid] = beta[tid];
    svec[768 + tid] = fin ? glw[tid] : 0.f;

    // ldmatrix per-lane byte offsets (within a stage)
    const uint32_t a_off = (uint32_t)((wm * 32 + (lane & 15)) * 80 + (lane >> 4) * 16);
    const uint32_t b_row = (uint32_t)(wn * 64 + ((lane & 7) | ((lane >> 4) << 3)));
    const uint32_t b_off = b_row * 80 + (((lane >> 3) & 1) * 16);

    float acc[2][8][4];
#pragma unroll
    for (int mt = 0; mt < 2; mt++)
#pragma unroll
        for (int nt = 0; nt < 8; nt++)
#pragma unroll
            for (int i = 0; i < 4; i++) acc[mt][nt][i] = 0.f;

    // prologue: chunks 0, 1 in flight
    load_A(stage0,         0, tid, l0, rowbase, Ah);
    CP_COMMIT();
    load_A(stage0 + STAGE, 1, tid, l0, rowbase, Ah);
    CP_COMMIT();
    if (tid == 0) {
        MBAR_EXPECT(mbar0, B_CHUNK_BYTES);
        CP_BULK(stage0 + SB, Wimg, B_CHUNK_BYTES, mbar0);
        MBAR_EXPECT(mbar0 + 8, B_CHUNK_BYTES);
        CP_BULK(stage0 + STAGE + SB, Wimg + B_CHUNK_U32, B_CHUNK_BYTES, mbar0 + 8);
    }

    int stg_idx = 0;
    for (int c = 0; c < 24; ++c) {
        const uint32_t stg = stage0 + stg_idx * STAGE;
        if (c < 23) CP_WAIT(1); else CP_WAIT(0);
        if (tid == 0) MBAR_WAIT(mbar0 + 8 * stg_idx, (c / 3) & 1);
        __syncthreads();

        // issue loads for c+2 (lands while computing c, c+1)
        if (c + 2 < 24) {
            int nidx = stg_idx + 2; if (nidx >= 3) nidx -= 3;
            load_A(stage0 + nidx * STAGE, c + 2, tid, l0, rowbase, Ah);
            CP_COMMIT();
            if (tid == 0) {
                MBAR_EXPECT(mbar0 + 8 * nidx, B_CHUNK_BYTES);
                CP_BULK(stage0 + nidx * STAGE + SB, Wimg + (c + 2) * B_CHUNK_U32,
                        B_CHUNK_BYTES, mbar0 + 8 * nidx);
            }
        }

#pragma unroll
        for (int kt = 0; kt < 2; ++kt) {
            uint32_t ah[2][4];
#pragma unroll
            for (int mt = 0; mt < 2; ++mt)
                LDSM_X4(ah[mt], stg + SA + a_off + mt * (16 * 80) + kt * 32);
#pragma unroll
            for (int j = 0; j < 4; ++j) {          // covers nt = 2j, 2j+1
                uint32_t bh[4];
                LDSM_X4(bh, stg + SB + b_off + j * (16 * 80) + kt * 32);
#pragma unroll
                for (int h = 0; h < 2; ++h)
#pragma unroll
                    for (int mt = 0; mt < 2; ++mt)
                        mma16816(acc[mt][j * 2 + h], ah[mt], bh[h * 2], bh[h * 2 + 1]);
            }
        }
        if (++stg_idx == 3) stg_idx = 0;
    }
    __syncthreads();   // stage region free -> epilogue overlay

    // ----- epilogue -----
    float* pa  = (float*)(smem + STAGE0_OFF);     // [3][64][4]
    float* smu = pa + 3 * 64 * 4;                 // [64]
    float* srs = smu + 64;                        // [64]

#pragma unroll
    for (int mt = 0; mt < 2; ++mt)
#pragma unroll
        for (int hf = 0; hf < 2; ++hf) {
            float s = 0.f, sq = 0.f, sd = 0.f;
#pragma unroll
            for (int nt = 0; nt < 8; ++nt) {
                int col = wn * 64 + nt * 8 + 2 * tig;
                float v0 = fmaxf(acc[mt][nt][hf * 2 + 0] + svec[col], 0.f);
                float v1 = fmaxf(acc[mt][nt][hf * 2 + 1] + svec[col + 1], 0.f);
                acc[mt][nt][hf * 2 + 0] = v0;
                acc[mt][nt][hf * 2 + 1] = v1;
                s += v0 + v1;
                sq += v0 * v0 + v1 * v1;
                if (fin) sd += v0 * svec[768 + col] + v1 * svec[768 + col + 1];
            }
            s  += __shfl_xor_sync(0xffffffffu, s, 1);
            s  += __shfl_xor_sync(0xffffffffu, s, 2);
            sq += __shfl_xor_sync(0xffffffffu, sq, 1);
            sq += __shfl_xor_sync(0xffffffffu, sq, 2);
            if (fin) {
                sd += __shfl_xor_sync(0xffffffffu, sd, 1);
                sd += __shfl_xor_sync(0xffffffffu, sd, 2);
            }
            if (tig == 0) {
                int row = wm * 32 + mt * 16 + hf * 8 + grp;
                pa[0 * 256 + row * 4 + wn] = s;
                pa[1 * 256 + row * 4 + wn] = sq;
                if (fin) pa[2 * 256 + row * 4 + wn] = sd;
            }
        }
    __syncthreads();

    if (tid < 64) {
        int row = tid;
        float s  = pa[row * 4] + pa[row * 4 + 1] + pa[row * 4 + 2] + pa[row * 4 + 3];
        float sq = pa[256 + row * 4] + pa[256 + row * 4 + 1] +
                   pa[256 + row * 4 + 2] + pa[256 + row * 4 + 3];
        float mu  = s * (1.f / 256.f);
        float var = sq * (1.f / 256.f) - mu * mu;
        float rs  = rsqrtf(var + 1e-5f);
        if (fin) {
            float s3 = pa[512 + row * 4] + pa[512 + row * 4 + 1] +
                       pa[512 + row * 4 + 2] + pa[512 + row * 4 + 3];
            dur[(size_t)tile * 64 + row] = expf(rs * (s3 - mu * scal[0]) + scal[1]);
        } else {
            smu[row] = mu;
            srs[row] = rs;
        }
    }

    if (!fin) {
        __syncthreads();
#pragma unroll
        for (int mt = 0; mt < 2; ++mt)
#pragma unroll
            for (int hf = 0; hf < 2; ++hf) {
                int row = wm * 32 + mt * 16 + hf * 8 + grp;
                float mu = smu[row], rs = srs[row];
#pragma unroll
                for (int nt = 0; nt < 8; ++nt) {
                    int col = wn * 64 + nt * 8 + 2 * tig;
                    float v0 = (acc[mt][nt][hf * 2 + 0] - mu) * rs * svec[256 + col]     + svec[512 + col];
                    float v1 = (acc[mt][nt][hf * 2 + 1] - mu) * rs * svec[256 + col + 1] + svec[512 + col + 1];
                    __half2 pk = __floats2half2_rn(v0, v1);
                    *(uint32_t*)(outh + ((size_t)tile * 64 + row) * 256 + col) = *(uint32_t*)&pk;
                }
            }
        __syncthreads();   // all h1 writes done before publish
        flag_publish(tile);
    }
}

// ---------------------------------------------------------------------------
// Fused pipeline kernel: conv1 | cumsum | conv2(+lin+exp) | gather
// ---------------------------------------------------------------------------
__global__ void __launch_bounds__(256, 2)
fused_all(const __half* __restrict__ xh, __half* __restrict__ h1,
          const uint32_t* __restrict__ wimg1, const uint32_t* __restrict__ wimg2,
          const float* __restrict__ conv1_b, const float* __restrict__ ln1_g,
          const float* __restrict__ ln1_b,
          const float* __restrict__ conv2_b, const float* __restrict__ ln2_g,
          const float* __restrict__ ln2_b,
          const float* __restrict__ glw, const float* __restrict__ scal,
          const int* __restrict__ target, const float* __restrict__ x,
          float* __restrict__ out_gather, float* __restrict__ out_dpo,
          float* __restrict__ out_dur)
{
    extern __shared__ char smem[];
    const int blk = blockIdx.x;

    if (blk < BLK_CS) {
        conv_tile(blk, false, smem, xh, wimg1,
                  conv1_b, ln1_g, ln1_b, glw, scal, h1, nullptr);
    } else if (blk < BLK_C2) {
        cumsum_block(blk - BLK_CS, target, out_dpo, smem);
    } else if (blk < BLK_GA) {
        conv_tile(blk - BLK_C2, true, smem, h1, wimg2,
                  conv2_b, ln2_g, ln2_b, glw, scal, nullptr, out_dur);
    } else {
        gather_block(blk - BLK_GA, x, out_gather, smem);
    }
}

// ---------------------------------------------------------------------------
// Launch
// ---------------------------------------------------------------------------
extern "C" void kernel_launch(void* const* d_in, const int* in_sizes, int n_in,
                              void* d_out, int out_size)
{
    const float* x       = (const float*)d_in[0];
    const int*   target  = (const int*)  d_in[1];
    const float* conv1_w = (const float*)d_in[3];
    const float* conv1_b = (const float*)d_in[4];
    const float* ln1_g   = (const float*)d_in[5];
    const float* ln1_b   = (const float*)d_in[6];
    const float* conv2_w = (const float*)d_in[7];
    const float* conv2_b = (const float*)d_in[8];
    const float* ln2_g   = (const float*)d_in[9];
    const float* ln2_b   = (const float*)d_in[10];
    const float* lin_w   = (const float*)d_in[11];
    const float* lin_b   = (const float*)d_in[12];

    float* out_gather = (float*)d_out;                        // [B, T, D]
    float* out_dpo    = out_gather + (size_t)Bz * Tz * Dz;    // [B, L]
    float* out_dur    = out_dpo + (size_t)Bz * Lz;            // [B, L]

    __half *xh, *h1;
    uint32_t *wimg1, *wimg2;
    float *glw, *scal;
    cudaGetSymbolAddress((void**)&xh,    g_xh);
    cudaGetSymbolAddress((void**)&h1,    g_h1);
    cudaGetSymbolAddress((void**)&wimg1, g_wimg1);
    cudaGetSymbolAddress((void**)&wimg2, g_wimg2);
    cudaGetSymbolAddress((void**)&glw,   g_glw);
    cudaGetSymbolAddress((void**)&scal,  g_scal);

    cudaFuncSetAttribute(fused_all, cudaFuncAttributeMaxDynamicSharedMemorySize, CONV_SMEM);

    // Prep: x -> fp16 | weights -> chunk images | scalars + flag reset
    prep_all<<<PREP_TOTAL, 256>>>(x, xh, conv1_w, conv2_w, wimg1, wimg2,
                                  ln2_g, ln2_b, lin_w, lin_b, glw, scal);

    // One fused pipeline kernel
    fused_all<<<BLK_TOTAL, 256, CONV_SMEM>>>(
        xh, h1, wimg1, wimg2,
        conv1_b, ln1_g, ln1_b, conv2_b, ln2_g, ln2_b,
        glw, scal, target, x, out_gather, out_dpo, out_dur);
}

// round 16
// speedup vs baseline: 4.1500x; 1.0361x over previous
#include <cuda_runtime.h>
#include <cuda_fp16.h>
#include <math.h>
#include <stdint.h>

#define Bz 32
#define Lz 768
#define Dz 256
#define Fz 256
#define Tz 3072

#define NCONV 384                       // conv tile CTAs per layer (M=64)
// fused grid block ranges
#define BLK_CS   NCONV                  // 32 cumsum
#define BLK_C2   (BLK_CS + Bz)          // 384 conv2 tiles
#define BLK_GA   (BLK_C2 + NCONV)       // 1536 gather
#define BLK_TOTAL (BLK_GA + 48 * Bz)    // 2336

// prep_all dispatch ranges
#define PREP_X_BLOCKS 3072              // 6,291,456 / 2048
#define PREP_W_BLOCKS 768               // 2 layers x 98,304 u32 / 256
#define PREP_TOTAL (PREP_X_BLOCKS + PREP_W_BLOCKS + 1)

#define NFLAGS (NCONV + Bz)

#define B_CHUNK_BYTES 20480             // 256 rows x 80B (pads included)
#define B_CHUNK_U32   5120

// ---------------------------------------------------------------------------
// Scratch (allocation-free: __device__ globals)
// ---------------------------------------------------------------------------
__device__ __half g_xh[Bz * Lz * Dz];          // x in fp16
__device__ __half g_h1[Bz * Lz * Fz];          // LN1 output in fp16
// weight images: exact smem stage layout per chunk (24 x 256rows x 80B)
__device__ uint32_t g_wimg1[24 * B_CHUNK_U32];
__device__ uint32_t g_wimg2[24 * B_CHUNK_U32];
__device__ float  g_glw[256];
__device__ float  g_scal[2];
__device__ int    g_cum[Bz * Lz];
__device__ int    g_flag[NFLAGS];

// ---------------------------------------------------------------------------
// helpers
// ---------------------------------------------------------------------------
__device__ __forceinline__ uint32_t smem_u32(const void* p) {
    uint32_t a;
    asm("{ .reg .u64 t; cvta.to.shared.u64 t, %1; cvt.u32.u64 %0, t; }"
        : "=r"(a) : "l"(p));
    return a;
}

__device__ __forceinline__ void cp16(uint32_t dst, const void* src, int src_bytes) {
    asm volatile("cp.async.cg.shared.global [%0], [%1], 16, %2;"
                 :: "r"(dst), "l"(src), "r"(src_bytes) : "memory");
}
#define CP_COMMIT() asm volatile("cp.async.commit_group;" ::: "memory")
#define CP_WAIT(n)  asm volatile("cp.async.wait_group %0;" :: "n"(n) : "memory")

// sm_90 bulk copy: one instruction per 20KB B tile, completes via mbarrier
#define CP_BULK(dst, src, bytes, mbar) \
    asm volatile("cp.async.bulk.shared::cta.global.mbarrier::complete_tx::bytes " \
                 "[%0], [%1], %2, [%3];" \
                 :: "r"(dst), "l"(src), "r"((uint32_t)(bytes)), "r"(mbar) : "memory")
#define MBAR_INIT(mbar, cnt) \
    asm volatile("mbarrier.init.shared.b64 [%0], %1;" :: "r"(mbar), "r"((uint32_t)(cnt)) : "memory")
#define MBAR_EXPECT(mbar, bytes) \
    asm volatile("mbarrier.arrive.expect_tx.shared.b64 _, [%0], %1;" \
                 :: "r"(mbar), "r"((uint32_t)(bytes)) : "memory")
#define MBAR_WAIT(mbar, parity) do { \
    uint32_t _m = (mbar), _p = (parity), _done; \
    asm volatile("{\n\t.reg .pred p;\n\t" \
        "mbarrier.try_wait.parity.acquire.cta.shared::cta.b64 p, [%1], %2;\n\t" \
        "selp.b32 %0, 1, 0, p;\n\t}" : "=r"(_done) : "r"(_m), "r"(_p) : "memory"); \
    if (!_done) { \
        asm volatile("{\n\t.reg .pred P1;\n\t" \
            "WAIT_LOOP_%=:\n\t" \
            "mbarrier.try_wait.parity.acquire.cta.shared::cta.b64 P1, [%0], %1, 0x989680;\n\t" \
            "@P1 bra.uni WAIT_DONE_%=;\n\t" \
            "bra.uni WAIT_LOOP_%=;\n\t" \
            "WAIT_DONE_%=:\n\t}" :: "r"(_m), "r"(_p) : "memory"); \
    } \
} while (0)

#define LDSM_X4(r, addr) \
    asm volatile("ldmatrix.sync.aligned.m8n8.x4.shared.b16 {%0,%1,%2,%3}, [%4];" \
        : "=r"((r)[0]), "=r"((r)[1]), "=r"((r)[2]), "=r"((r)[3]) : "r"(addr))

// fp16 MMA m16n8k16, fp32 accumulate (non-volatile: let ptxas schedule)
__device__ __forceinline__ void mma16816(float* c, const uint32_t* a,
                                         uint32_t b0, uint32_t b1)
{
    asm("mma.sync.aligned.m16n8k16.row.col.f32.f16.f16.f32 "
        "{%0,%1,%2,%3}, {%4,%5,%6,%7}, {%8,%9}, {%0,%1,%2,%3};\n"
        : "+f"(c[0]), "+f"(c[1]), "+f"(c[2]), "+f"(c[3])
        : "r"(a[0]), "r"(a[1]), "r"(a[2]), "r"(a[3]), "r"(b0), "r"(b1));
}

__device__ __forceinline__ void flag_publish(int idx) {
    __threadfence();
    if (threadIdx.x == 0) atomicExch(&g_flag[idx], 1);
}
__device__ __forceinline__ void flag_spin(int idx) {
    if (threadIdx.x == 0) {
        while (atomicAdd(&g_flag[idx], 0) == 0) __nanosleep(64);
    }
}

// ---------------------------------------------------------------------------
// Unified prep kernel (256 threads/block)
// ---------------------------------------------------------------------------
__global__ __launch_bounds__(256)
void prep_all(const float* __restrict__ x, __half* __restrict__ xh,
              const float* __restrict__ w1, const float* __restrict__ w2,
              uint32_t* __restrict__ img1, uint32_t* __restrict__ img2,
              const float* __restrict__ g, const float* __restrict__ bb,
              const float* __restrict__ lw, const float* __restrict__ lb,
              float* __restrict__ glw, float* __restrict__ scal)
{
    const int blk = blockIdx.x;
    const int t = threadIdx.x;

    if (blk < PREP_X_BLOCKS) {
        size_t i = ((size_t)blk * 256 + t) * 8;
        float4 f0 = *(const float4*)(x + i);
        float4 f1 = *(const float4*)(x + i + 4);
        __half2 h0 = __floats2half2_rn(f0.x, f0.y);
        __half2 h1 = __floats2half2_rn(f0.z, f0.w);
        __half2 h2 = __floats2half2_rn(f1.x, f1.y);
        __half2 h3 = __floats2half2_rn(f1.z, f1.w);
        uint4 v;
        v.x = *(uint32_t*)&h0; v.y = *(uint32_t*)&h1;
        v.z = *(uint32_t*)&h2; v.w = *(uint32_t*)&h3;
        *(uint4*)(xh + i) = v;
        return;
    }
    if (blk < PREP_X_BLOCKS + PREP_W_BLOCKS) {
        int e = blk - PREP_X_BLOCKS;                   // 0..767
        int sel = e >= 384;
        int idx = (e - sel * 384) * 256 + t;           // 0 .. 98303
        const float* w = sel ? w2 : w1;
        uint32_t* img = sel ? img2 : img1;
        int c   = idx >> 12;                            // chunk 0..23
        int rem = idx & 4095;
        int n   = rem >> 4;                             // cout 0..255
        int q   = rem & 15;                             // pair-in-chunk 0..15
        int tap = c >> 3;
        int p   = ((c & 7) << 4) + q;                   // cin pair 0..127
        float a = w[((size_t)(tap * 256 + 2 * p))     * 256 + n];
        float b = w[((size_t)(tap * 256 + 2 * p + 1)) * 256 + n];
        __half2 pk = __floats2half2_rn(a, b);
        img[c * B_CHUNK_U32 + n * 20 + q] = *(uint32_t*)&pk;
        return;
    }
    // scalars + flag reset
    {
        for (int i = t; i < NFLAGS; i += 256) g_flag[i] = 0;
        __shared__ float sg[8], sb[8];
        float lwv = lw[t];
        float gv = g[t] * lwv;
        float bv = bb[t] * lwv;
        glw[t] = gv;
#pragma unroll
        for (int o = 16; o; o >>= 1) {
            gv += __shfl_xor_sync(0xffffffffu, gv, o);
            bv += __shfl_xor_sync(0xffffffffu, bv, o);
        }
        if ((t & 31) == 0) { sg[t >> 5] = gv; sb[t >> 5] = bv; }
        __syncthreads();
        if (t == 0) {
            float G = 0.f, Bv = 0.f;
            for (int i = 0; i < 8; i++) { G += sg[i]; Bv += sb[i]; }
            scal[0] = G;
            scal[1] = Bv + lb[0];
        }
    }
}

// ---------------------------------------------------------------------------
// cumsum for one batch (256 threads, 3 elems each)
// ---------------------------------------------------------------------------
__device__ void cumsum_block(int b, const int* __restrict__ target,
                             float* __restrict__ dpo_out, char* smem)
{
    int* ps = (int*)smem;
    const int t = threadIdx.x;
    const size_t base = (size_t)b * Lz + 3 * t;
    int v0 = target[base], v1 = target[base + 1], v2 = target[base + 2];
    int s1 = v0 + v1, s2 = s1 + v2;
    ps[t] = s2;
    __syncthreads();
#pragma unroll
    for (int off = 1; off < 256; off <<= 1) {
        int u = (t >= off) ? ps[t - off] : 0;
        __syncthreads();
        ps[t] += u;
        __syncthreads();
    }
    int pre = (t > 0) ? ps[t - 1] : 0;
    g_cum[base]     = pre + v0;
    g_cum[base + 1] = pre + s1;
    g_cum[base + 2] = pre + s2;
    dpo_out[base]     = (float)v0;
    dpo_out[base + 1] = (float)v1;
    dpo_out[base + 2] = (float)v2;
    __syncthreads();
    flag_publish(NCONV + b);
}

// ---------------------------------------------------------------------------
// gather for one (batch, 64-t block): e in 0..1535
// ---------------------------------------------------------------------------
__device__ void gather_block(int e, const float* __restrict__ x,
                             float* __restrict__ dout, char* smem)
{
    int* cum = (int*)smem;
    const int b = e / 48;
    const int tpart = e % 48;
    const int tid = threadIdx.x;

    flag_spin(NCONV + b);
    __syncthreads();

    for (int i = tid; i < Lz; i += 256)
        cum[i] = g_cum[(size_t)b * Lz + i];
    __syncthreads();

    const int total = cum[Lz - 1];
    const int t0 = tpart * 64;
    const int sub  = tid & 63;
    const int tloc = tid >> 6;

    const float4* xrow = (const float4*)(x + (size_t)b * Lz * Dz);
    float4* orow = (float4*)(dout + (size_t)b * Tz * Dz);

#pragma unroll 4
    for (int it = 0; it < 16; ++it) {
        int t = t0 + it * 4 + tloc;
        int lo = 0, hi = Lz;
        while (lo < hi) {
            int mid = (lo + hi) >> 1;
            if (cum[mid] <= t) lo = mid + 1; else hi = mid;
        }
        float4 v;
        if (t < total) {
            int idx = min(lo, Lz - 1);
            v = xrow[(size_t)idx * 64 + sub];
        } else {
            v = make_float4(0.0f, 0.0f, 0.0f, 0.0f);
        }
        orow[(size_t)t * 64 + sub] = v;
    }
}

// ---------------------------------------------------------------------------
// conv tile: M=64 x N=256, 256 threads (8 warps 2M x 4N), fp16 single-pass.
// A: 66 rows x 256 fp16 (stride 528B, ldmatrix conflict-free), loaded ONCE in
//    prologue; taps index it by row offset (+0/+1/+2).
// B: one 20KB bulk copy per chunk, 3-stage mbarrier ring.
// 24 chunks of K=32. 2 CTAs/SM.
// ---------------------------------------------------------------------------
#define A_STRIDE 528
#define A_ROWS 66
#define A_BYTES (A_ROWS * A_STRIDE)            // 34848
#define A_SEGS  (A_ROWS * 32)                  // 2112 x 16B
#define MBAR_OFF 4096                          // 3 x 8B mbarriers
#define A_OFF 4224
#define SB0_OFF ((A_OFF + A_BYTES + 127) & ~127)   // 39104
#define CONV_SMEM (SB0_OFF + 3 * B_CHUNK_BYTES)    // 100544

__device__ void conv_tile(
    int tile, bool fin, char* smem,
    const __half* __restrict__ Ah, const uint32_t* __restrict__ Wimg,
    const float* __restrict__ bias, const float* __restrict__ gamma,
    const float* __restrict__ beta, const float* __restrict__ glw,
    const float* __restrict__ scal,
    __half* __restrict__ outh, float* __restrict__ dur)
{
    const uint32_t sb = smem_u32(smem);
    float* svec = (float*)smem;                       // [4][256]
    const uint32_t mbar0 = sb + MBAR_OFF;
    const uint32_t sA    = sb + A_OFF;
    const uint32_t sB0   = sb + SB0_OFF;

    const int tid = threadIdx.x;
    const int wid = tid >> 5, lane = tid & 31;
    const int wm = wid >> 2, wn = wid & 3;            // 2M x 4N warps
    const int grp = lane >> 2, tig = lane & 3;

    const int batch = tile / 12;
    const int part  = tile % 12;
    const int l0 = part * 64;
    const size_t rowbase = (size_t)batch * Lz;

    if (tid == 0) {
        MBAR_INIT(mbar0,      1);
        MBAR_INIT(mbar0 + 8,  1);
        MBAR_INIT(mbar0 + 16, 1);
    }
    if (fin) {
        flag_spin(tile);
        if (part > 0)  flag_spin(tile - 1);
        if (part < 11) flag_spin(tile + 1);
        __threadfence();
    }
    __syncthreads();

    svec[tid]       = bias[tid];
    svec[256 + tid] = gamma[tid];
    svec[512 + tid] = beta[tid];
    svec[768 + tid] = fin ? glw[tid] : 0.f;

    // ---- prologue: A loaded once (66 rows, zfill outside batch) ----
#pragma unroll
    for (int i = 0; i < 9; ++i) {
        int idx = tid + (i << 8);
        if (idx < A_SEGS) {
            int row = idx >> 5, seg = idx & 31;       // row 0..65, seg 0..31
            int gl = l0 + row - 1;
            int ok = (gl >= 0 && gl < Lz) ? 16 : 0;
            int glc = gl < 0 ? 0 : (gl >= Lz ? Lz - 1 : gl);
            cp16(sA + row * A_STRIDE + seg * 16,
                 Ah + ((rowbase + glc) << 8) + (seg << 3), ok);
        }
    }
    CP_COMMIT();
    // B bulks for chunks 0, 1
    if (tid == 0) {
        MBAR_EXPECT(mbar0, B_CHUNK_BYTES);
        CP_BULK(sB0, Wimg, B_CHUNK_BYTES, mbar0);
        MBAR_EXPECT(mbar0 + 8, B_CHUNK_BYTES);
        CP_BULK(sB0 + B_CHUNK_BYTES, Wimg + B_CHUNK_U32, B_CHUNK_BYTES, mbar0 + 8);
    }
    CP_WAIT(0);   // A resident

    // ldmatrix per-lane byte offsets
    const uint32_t a_off = (uint32_t)((wm * 32 + (lane & 15)) * A_STRIDE + (lane >> 4) * 16);
    const uint32_t b_row = (uint32_t)(wn * 64 + ((lane & 7) | ((lane >> 4) << 3)));
    const uint32_t b_off = b_row * 80 + (((lane >> 3) & 1) * 16);

    float acc[2][8][4];
#pragma unroll
    for (int mt = 0; mt < 2; mt++)
#pragma unroll
        for (int nt = 0; nt < 8; nt++)
#pragma unroll
            for (int i = 0; i < 4; i++) acc[mt][nt][i] = 0.f;

    int stg_idx = 0;
    for (int c = 0; c < 24; ++c) {
        const int tap  = c >> 3;
        const int cin0 = (c & 7) << 5;
        const uint32_t stgB = sB0 + stg_idx * B_CHUNK_BYTES;
        const uint32_t aBase = sA + a_off + tap * A_STRIDE + cin0 * 2;

        if (tid == 0) MBAR_WAIT(mbar0 + 8 * stg_idx, (c / 3) & 1);
        __syncthreads();

        // refill stage (c+2)%3 — safe: barrier above means chunk c-1 fully read
        if (c + 2 < 24) {
            int nidx = stg_idx + 2; if (nidx >= 3) nidx -= 3;
            if (tid == 0) {
                MBAR_EXPECT(mbar0 + 8 * nidx, B_CHUNK_BYTES);
                CP_BULK(sB0 + nidx * B_CHUNK_BYTES, Wimg + (c + 2) * B_CHUNK_U32,
                        B_CHUNK_BYTES, mbar0 + 8 * nidx);
            }
        }

#pragma unroll
        for (int kt = 0; kt < 2; ++kt) {
            uint32_t ah[2][4];
#pragma unroll
            for (int mt = 0; mt < 2; ++mt)
                LDSM_X4(ah[mt], aBase + mt * (16 * A_STRIDE) + kt * 32);
#pragma unroll
            for (int j = 0; j < 4; ++j) {          // covers nt = 2j, 2j+1
                uint32_t bh[4];
                LDSM_X4(bh, stgB + b_off + j * (16 * 80) + kt * 32);
#pragma unroll
                for (int h = 0; h < 2; ++h)
#pragma unroll
                    for (int mt = 0; mt < 2; ++mt)
                        mma16816(acc[mt][j * 2 + h], ah[mt], bh[h * 2], bh[h * 2 + 1]);
            }
        }
        if (++stg_idx == 3) stg_idx = 0;
    }
    __syncthreads();   // A region free -> epilogue overlay

    // ----- epilogue (overlay on A region) -----
    float* pa  = (float*)(smem + A_OFF);          // [3][64][4]
    float* smu = pa + 3 * 64 * 4;                 // [64]
    float* srs = smu + 64;                        // [64]

#pragma unroll
    for (int mt = 0; mt < 2; ++mt)
#pragma unroll
        for (int hf = 0; hf < 2; ++hf) {
            float s = 0.f, sq = 0.f, sd = 0.f;
#pragma unroll
            for (int nt = 0; nt < 8; ++nt) {
                int col = wn * 64 + nt * 8 + 2 * tig;
                float v0 = fmaxf(acc[mt][nt][hf * 2 + 0] + svec[col], 0.f);
                float v1 = fmaxf(acc[mt][nt][hf * 2 + 1] + svec[col + 1], 0.f);
                acc[mt][nt][hf * 2 + 0] = v0;
                acc[mt][nt][hf * 2 + 1] = v1;
                s += v0 + v1;
                sq += v0 * v0 + v1 * v1;
                if (fin) sd += v0 * svec[768 + col] + v1 * svec[768 + col + 1];
            }
            s  += __shfl_xor_sync(0xffffffffu, s, 1);
            s  += __shfl_xor_sync(0xffffffffu, s, 2);
            sq += __shfl_xor_sync(0xffffffffu, sq, 1);
            sq += __shfl_xor_sync(0xffffffffu, sq, 2);
            if (fin) {
                sd += __shfl_xor_sync(0xffffffffu, sd, 1);
                sd += __shfl_xor_sync(0xffffffffu, sd, 2);
            }
            if (tig == 0) {
                int row = wm * 32 + mt * 16 + hf * 8 + grp;
                pa[0 * 256 + row * 4 + wn] = s;
                pa[1 * 256 + row * 4 + wn] = sq;
                if (fin) pa[2 * 256 + row * 4 + wn] = sd;
            }
        }
    __syncthreads();

    if (tid < 64) {
        int row = tid;
        float s  = pa[row * 4] + pa[row * 4 + 1] + pa[row * 4 + 2] + pa[row * 4 + 3];
        float sq = pa[256 + row * 4] + pa[256 + row * 4 + 1] +
                   pa[256 + row * 4 + 2] + pa[256 + row * 4 + 3];
        float mu  = s * (1.f / 256.f);
        float var = sq * (1.f / 256.f) - mu * mu;
        float rs  = rsqrtf(var + 1e-5f);
        if (fin) {
            float s3 = pa[512 + row * 4] + pa[512 + row * 4 + 1] +
                       pa[512 + row * 4 + 2] + pa[512 + row * 4 + 3];
            dur[(size_t)tile * 64 + row] = expf(rs * (s3 - mu * scal[0]) + scal[1]);
        } else {
            smu[row] = mu;
            srs[row] = rs;
        }
    }

    if (!fin) {
        __syncthreads();
#pragma unroll
        for (int mt = 0; mt < 2; ++mt)
#pragma unroll
            for (int hf = 0; hf < 2; ++hf) {
                int row = wm * 32 + mt * 16 + hf * 8 + grp;
                float mu = smu[row], rs = srs[row];
#pragma unroll
                for (int nt = 0; nt < 8; ++nt) {
                    int col = wn * 64 + nt * 8 + 2 * tig;
                    float v0 = (acc[mt][nt][hf * 2 + 0] - mu) * rs * svec[256 + col]     + svec[512 + col];
                    float v1 = (acc[mt][nt][hf * 2 + 1] - mu) * rs * svec[256 + col + 1] + svec[512 + col + 1];
                    __half2 pk = __floats2half2_rn(v0, v1);
                    *(uint32_t*)(outh + ((size_t)tile * 64 + row) * 256 + col) = *(uint32_t*)&pk;
                }
            }
        __syncthreads();   // all h1 writes done before publish
        flag_publish(tile);
    }
}

// ---------------------------------------------------------------------------
// Fused pipeline kernel: conv1 | cumsum | conv2(+lin+exp) | gather
// ---------------------------------------------------------------------------
__global__ void __launch_bounds__(256, 2)
fused_all(const __half* __restrict__ xh, __half* __restrict__ h1,
          const uint32_t* __restrict__ wimg1, const uint32_t* __restrict__ wimg2,
          const float* __restrict__ conv1_b, const float* __restrict__ ln1_g,
          const float* __restrict__ ln1_b,
          const float* __restrict__ conv2_b, const float* __restrict__ ln2_g,
          const float* __restrict__ ln2_b,
          const float* __restrict__ glw, const float* __restrict__ scal,
          const int* __restrict__ target, const float* __restrict__ x,
          float* __restrict__ out_gather, float* __restrict__ out_dpo,
          float* __restrict__ out_dur)
{
    extern __shared__ char smem[];
    const int blk = blockIdx.x;

    if (blk < BLK_CS) {
        conv_tile(blk, false, smem, xh, wimg1,
                  conv1_b, ln1_g, ln1_b, glw, scal, h1, nullptr);
    } else if (blk < BLK_C2) {
        cumsum_block(blk - BLK_CS, target, out_dpo, smem);
    } else if (blk < BLK_GA) {
        conv_tile(blk - BLK_C2, true, smem, h1, wimg2,
                  conv2_b, ln2_g, ln2_b, glw, scal, nullptr, out_dur);
    } else {
        gather_block(blk - BLK_GA, x, out_gather, smem);
    }
}

// ---------------------------------------------------------------------------
// Launch
// ---------------------------------------------------------------------------
extern "C" void kernel_launch(void* const* d_in, const int* in_sizes, int n_in,
                              void* d_out, int out_size)
{
    const float* x       = (const float*)d_in[0];
    const int*   target  = (const int*)  d_in[1];
    const float* conv1_w = (const float*)d_in[3];
    const float* conv1_b = (const float*)d_in[4];
    const float* ln1_g   = (const float*)d_in[5];
    const float* ln1_b   = (const float*)d_in[6];
    const float* conv2_w = (const float*)d_in[7];
    const float* conv2_b = (const float*)d_in[8];
    const float* ln2_g   = (const float*)d_in[9];
    const float* ln2_b   = (const float*)d_in[10];
    const float* lin_w   = (const float*)d_in[11];
    const float* lin_b   = (const float*)d_in[12];

    float* out_gather = (float*)d_out;                        // [B, T, D]
    float* out_dpo    = out_gather + (size_t)Bz * Tz * Dz;    // [B, L]
    float* out_dur    = out_dpo + (size_t)Bz * Lz;            // [B, L]

    __half *xh, *h1;
    uint32_t *wimg1, *wimg2;
    float *glw, *scal;
    cudaGetSymbolAddress((void**)&xh,    g_xh);
    cudaGetSymbolAddress((void**)&h1,    g_h1);
    cudaGetSymbolAddress((void**)&wimg1, g_wimg1);
    cudaGetSymbolAddress((void**)&wimg2, g_wimg2);
    cudaGetSymbolAddress((void**)&glw,   g_glw);
    cudaGetSymbolAddress((void**)&scal,  g_scal);

    cudaFuncSetAttribute(fused_all, cudaFuncAttributeMaxDynamicSharedMemorySize, CONV_SMEM);

    // Prep: x -> fp16 | weights -> chunk images | scalars + flag reset
    prep_all<<<PREP_TOTAL, 256>>>(x, xh, conv1_w, conv2_w, wimg1, wimg2,
                                  ln2_g, ln2_b, lin_w, lin_b, glw, scal);

    // One fused pipeline kernel
    fused_all<<<BLK_TOTAL, 256, CONV_SMEM>>>(
        xh, h1, wimg1, wimg2,
        conv1_b, ln1_g, ln1_b, conv2_b, ln2_g, ln2_b,
        glw, scal, target, x, out_gather, out_dpo, out_dur);
}